// round 11
// baseline (speedup 1.0000x reference)
#include <cuda_runtime.h>
#include <cuda_bf16.h>
#include <math.h>
#include <stdint.h>

// ---------------------------------------------------------------------------
// DirectRegressionHead: 2-layer GRU encoder (7 steps) + 12-step GRU decoder.
// B=32768, H=256, CTX=128, PRED=12.
// bf16x3 split-precision mma.sync.m16n8k16, fp32 accumulate.
// Activations kept as pre-swizzled SW128 bf16 hi/lo 128x64 tiles in global;
// A and W staged by double-buffered cp.async, prefetched one chunk ahead.
// 256 thr, N=32 gate-cols, cell smem 112KB -> 2 CTAs/SM.
// ---------------------------------------------------------------------------

#define BMAX 32768
#define HDIM 256
#define CTXD 128
#define PRED 12

// packed weight layout (bf16 elems, hi; lo at +WTOT)
// cell weights: [chunk][nb(8)][96][64] pre-swizzled; PA: [chunk][192][64]
#define O_WHH0 0L
#define O_WIH1 196608L
#define O_WHH1 393216L
#define O_WHHS 589824L
#define O_WCTX 786432L
#define O_PA   884736L
#define WTOT   933888L

// smem buffer layout (bytes, per buffer): Ahi 0 | Alo 16384 | Whi 32768 | Wlo 45056
#define BUFSZ   57344
#define OFF_WDS 73728          // wd_s (3KB), aliases buf1 tail, loaded post-GEMM
#define GRU_SMEM  114688       // 2 buffers
#define OFF_D1  114688
#define OFF_WSM 215040
#define PROJ_SMEM 217632

// --- static device scratch ---
__device__ __nv_bfloat16 g_t0a[2 * (size_t)BMAX * HDIM];  // hi, lo at +BMAX*256
__device__ __nv_bfloat16 g_t0b[2 * (size_t)BMAX * HDIM];
__device__ __nv_bfloat16 g_t1a[2 * (size_t)BMAX * HDIM];
__device__ __nv_bfloat16 g_t1b[2 * (size_t)BMAX * HDIM];
__device__ __nv_bfloat16 g_ctile[2 * (size_t)BMAX * CTXD]; // lo at +BMAX*128
__device__ float g_obsin[8 * BMAX * 6];
__device__ float g_dynA[BMAX * 6];
__device__ float g_dynB[BMAX * 6];
__device__ float g_gictx[(size_t)BMAX * 768];
__device__ float g_wdyn0[768 * 8];
__device__ float g_wdynS[768 * 8];
__device__ __nv_bfloat16 g_wpack[2 * WTOT];

// ---------------- async-copy / mma helpers ----------------
__device__ __forceinline__ void cp16(void* dst, const void* src) {
    uint32_t d = (uint32_t)__cvta_generic_to_shared(dst);
    asm volatile("cp.async.cg.shared.global [%0], [%1], 16;" :: "r"(d), "l"(src));
}
__device__ __forceinline__ void cp_commit() { asm volatile("cp.async.commit_group;"); }
__device__ __forceinline__ void cp_wait0() { asm volatile("cp.async.wait_group 0;"); }
__device__ __forceinline__ void cp_wait1() { asm volatile("cp.async.wait_group 1;"); }

__device__ __forceinline__ void mma_bf16(float* c, const uint32_t* a, uint32_t b0, uint32_t b1) {
    asm volatile(
        "mma.sync.aligned.m16n8k16.row.col.f32.bf16.bf16.f32 "
        "{%0,%1,%2,%3}, {%4,%5,%6,%7}, {%8,%9}, {%0,%1,%2,%3};\n"
        : "+f"(c[0]), "+f"(c[1]), "+f"(c[2]), "+f"(c[3])
        : "r"(a[0]), "r"(a[1]), "r"(a[2]), "r"(a[3]), "r"(b0), "r"(b1));
}

// swizzled ldmatrix: tile rows of 128B, SW128 (byte o ^= (row&7)<<4)
__device__ __forceinline__ void ldsm4s(uint32_t* r, char* base, int row, int col, int lane) {
    int g = lane >> 3, rr = lane & 7;
    int r2 = row + (g & 1) * 8 + rr;
    int o = r2 * 128 + (col + (g >> 1) * 8) * 2;
    o ^= (r2 & 7) << 4;
    uint32_t a = (uint32_t)__cvta_generic_to_shared(base + o);
    asm volatile("ldmatrix.sync.aligned.m8n8.x4.shared.b16 {%0,%1,%2,%3}, [%4];"
                 : "=r"(r[0]), "=r"(r[1]), "=r"(r[2]), "=r"(r[3]) : "r"(a));
}
__device__ __forceinline__ void ldsm2s(uint32_t* r, char* base, int row, int col, int lane) {
    int l = lane & 15;
    int r2 = row + (l & 7);
    int o = r2 * 128 + (col + (l >> 3) * 8) * 2;
    o ^= (r2 & 7) << 4;
    uint32_t a = (uint32_t)__cvta_generic_to_shared(base + o);
    asm volatile("ldmatrix.sync.aligned.m8n8.x2.shared.b16 {%0,%1}, [%2];"
                 : "=r"(r[0]), "=r"(r[1]) : "r"(a));
}

template<bool ALT>
__device__ __forceinline__ void mma_all(float (&accA)[2][6][4], float (&accH)[2][2][4],
                                        uint32_t a[2][4], uint32_t b[6][2]) {
#pragma unroll
    for (int mf = 0; mf < 2; mf++)
#pragma unroll
        for (int f = 0; f < 6; f++) {
            float* c = (ALT && f >= 4) ? accH[mf][f - 4] : accA[mf][f];
            mma_bf16(c, a[mf], b[f][0], b[f][1]);
        }
}

// mma over one staged buffer: A 128x64 hi/lo, W 96x64 hi/lo (all SW128 tiles)
template<bool ALT>
__device__ __forceinline__ void mma_tile(char* bb, float (&accA)[2][6][4],
                                         float (&accH)[2][2][4],
                                         int mw, int nw, int lane) {
    char* Ahi = bb;
    char* Alo = bb + 16384;
    char* Whi = bb + 32768;
    char* Wlo = bb + 45056;
#pragma unroll
    for (int ks = 0; ks < 4; ks++) {
        uint32_t ah[2][4], al[2][4], b[6][2];
        ldsm4s(ah[0], Ahi, mw * 32,      ks * 16, lane);
        ldsm4s(ah[1], Ahi, mw * 32 + 16, ks * 16, lane);
        ldsm4s(al[0], Alo, mw * 32,      ks * 16, lane);
        ldsm4s(al[1], Alo, mw * 32 + 16, ks * 16, lane);
#pragma unroll
        for (int f = 0; f < 6; f++) ldsm2s(b[f], Whi, (f * 2 + nw) * 8, ks * 16, lane);
        mma_all<ALT>(accA, accH, ah, b);   // hi*hi
        mma_all<ALT>(accA, accH, al, b);   // lo*hi
#pragma unroll
        for (int f = 0; f < 6; f++) ldsm2s(b[f], Wlo, (f * 2 + nw) * 8, ks * 16, lane);
        mma_all<ALT>(accA, accH, ah, b);   // hi*lo
    }
}

// stage one chunk (A tile + W slice) into buffer bb via linear cp.async
__device__ __forceinline__ void stage_chunk(char* bb, const __nv_bfloat16* ahi,
                                            size_t aLoE, long wo, int tid) {
    const char* ah = (const char*)ahi;
    const char* al = (const char*)(ahi + aLoE);
    for (int i = tid; i < 1024; i += 256) {
        cp16(bb + i * 16, ah + i * 16);
        cp16(bb + 16384 + i * 16, al + i * 16);
    }
    const char* wh = (const char*)(g_wpack + wo);
    const char* wl = (const char*)(g_wpack + WTOT + wo);
    for (int i = tid; i < 768; i += 256) {
        cp16(bb + 32768 + i * 16, wh + i * 16);
        cp16(bb + 45056 + i * 16, wl + i * 16);
    }
    cp_commit();
}

// ---------------- pack / prep ----------------
__global__ void zero_kernel(float* __restrict__ p, int n) {
    int s = gridDim.x * blockDim.x;
    for (int i = blockIdx.x * blockDim.x + threadIdx.x; i * 4 < n; i += s)
        ((float4*)p)[i] = make_float4(0.f, 0.f, 0.f, 0.f);
}

// cell weight pack: [768 x ld] -> [chunk][nb(8)][96][64] pre-swizzled hi/lo
__global__ void pack_cellw(const float* __restrict__ W, int ld, int koff,
                           int Kreal, int nch, long dst, __nv_bfloat16* __restrict__ wp) {
    int i = blockIdx.x * blockDim.x + threadIdx.x;
    if (i >= nch * 8 * 96 * 64) return;
    int t = i / (8 * 96 * 64);
    int rem = i - t * 8 * 96 * 64;
    int nb = rem / (96 * 64);
    int rem2 = rem - nb * 96 * 64;
    int r = rem2 >> 6, c = rem2 & 63;
    int p = r >> 5, j = r & 31;
    int srcrow = p * 256 + nb * 32 + j;
    int k = t * 64 + c;
    float v = (k < Kreal) ? W[(size_t)srcrow * ld + koff + k] : 0.f;
    __nv_bfloat16 h = __float2bfloat16(v);
    long o = dst + ((long)(t * 8 + nb) * 96 + r) * 64 + (c ^ ((r & 7) << 3));
    wp[o] = h;
    wp[WTOT + o] = __float2bfloat16(v - __bfloat162float(h));
}

// P1/A1 pack: [192 x 256] -> [chunk][192][64] pre-swizzled hi/lo
__global__ void pack_paw(const float* __restrict__ P1, const float* __restrict__ A1,
                         __nv_bfloat16* __restrict__ wp) {
    int i = blockIdx.x * blockDim.x + threadIdx.x;
    if (i >= 4 * 192 * 64) return;
    int t = i / (192 * 64);
    int rem = i - t * 192 * 64;
    int r = rem >> 6, c = rem & 63;
    int k = t * 64 + c;
    float v = (r < 128) ? P1[(size_t)r * 256 + k] : A1[(size_t)(r - 128) * 256 + k];
    __nv_bfloat16 h = __float2bfloat16(v);
    long o = O_PA + ((long)t * 192 + r) * 64 + (c ^ ((r & 7) << 3));
    wp[o] = h;
    wp[WTOT + o] = __float2bfloat16(v - __bfloat162float(h));
}

__global__ void wdyn_pack_kernel(const float* __restrict__ s, int ld, int koff,
                                 float* __restrict__ d) {
    int i = blockIdx.x * blockDim.x + threadIdx.x;
    if (i >= 768 * 8) return;
    int r = i >> 3, q = i & 7;
    d[i] = (q < 6) ? s[(size_t)r * ld + koff + q] : 0.f;
}

__global__ void prep_kernel(const float* __restrict__ traj, const float* __restrict__ me,
                            float* __restrict__ obsin, float* __restrict__ dyn, int B, int T) {
    int b = blockIdx.x * blockDim.x + threadIdx.x;
    if (b >= B) return;
    float vx[8], vy[8], mx[8], my_[8];
    int TS = T - 1; if (TS > 8) TS = 8;
    for (int t = 0; t < TS; t++) {
        vx[t]  = traj[((size_t)(t + 1) * B + b) * 2 + 0] - traj[((size_t)t * B + b) * 2 + 0];
        vy[t]  = traj[((size_t)(t + 1) * B + b) * 2 + 1] - traj[((size_t)t * B + b) * 2 + 1];
        mx[t]  = me[((size_t)(t + 1) * B + b) * 2 + 0] - me[((size_t)t * B + b) * 2 + 0];
        my_[t] = me[((size_t)(t + 1) * B + b) * 2 + 1] - me[((size_t)t * B + b) * 2 + 1];
    }
    for (int t = 0; t < TS; t++) {
        int ta = (t == 0) ? 1 : t;
        float* o = obsin + ((size_t)t * B + b) * 6;
        o[0] = vx[t]; o[1] = vy[t]; o[2] = mx[t]; o[3] = my_[t];
        o[4] = vx[ta] - vx[ta - 1]; o[5] = vy[ta] - vy[ta - 1];
    }
    dyn[(size_t)b * 6 + 0] = vx[TS - 1];
    dyn[(size_t)b * 6 + 1] = vy[TS - 1];
    dyn[(size_t)b * 6 + 2] = vx[TS - 1] - vx[TS - 2];
    dyn[(size_t)b * 6 + 3] = vy[TS - 1] - vy[TS - 2];
    dyn[(size_t)b * 6 + 4] = mx[TS - 1];
    dyn[(size_t)b * 6 + 5] = my_[TS - 1];
}

// ctx projection -> pre-swizzled bf16 hi/lo tiles
__global__ __launch_bounds__(256) void ctx_kernel(const float* __restrict__ ctx,
                                                  const float* __restrict__ Cw,
                                                  const float* __restrict__ cb,
                                                  __nv_bfloat16* __restrict__ ctile, int B) {
    __shared__ float Cs[64][128];
    __shared__ float Wc[16][128];
    int tid = threadIdx.x, m0 = blockIdx.x * 64;
    for (int i = tid; i < 2048; i += 256) {
        int m = m0 + (i * 4) / 128;
        float4 v = make_float4(0.f, 0.f, 0.f, 0.f);
        if (m < B) v = *(const float4*)&ctx[(size_t)m0 * 128 + i * 4];
        ((float4*)Cs)[i] = v;
    }
    __syncthreads();
    int w = tid >> 5, lane = tid & 31;
    float acc[8][4];
#pragma unroll
    for (int i = 0; i < 8; i++)
#pragma unroll
        for (int u = 0; u < 4; u++) acc[i][u] = 0.f;
    for (int k0 = 0; k0 < 128; k0 += 16) {
        for (int i = tid; i < 2048; i += 256) {
            int kk = i & 15, u = i >> 4;
            Wc[kk][u] = Cw[(size_t)u * 128 + k0 + kk];
        }
        __syncthreads();
#pragma unroll
        for (int kk = 0; kk < 16; kk++) {
            float wv[4];
#pragma unroll
            for (int u = 0; u < 4; u++) wv[u] = Wc[kk][lane * 4 + u];
#pragma unroll
            for (int i = 0; i < 8; i++) {
                float a = Cs[w * 8 + i][k0 + kk];
#pragma unroll
                for (int u = 0; u < 4; u++) acc[i][u] += a * wv[u];
            }
        }
        __syncthreads();
    }
#pragma unroll
    for (int i = 0; i < 8; i++) {
        int m = m0 + w * 8 + i;
        if (m >= B) continue;
        int row = m & 127;
#pragma unroll
        for (int u = 0; u < 4; u++) {
            int ug = lane * 4 + u;
            float v = acc[i][u] + cb[ug];
            int kc = ug >> 6, cc = ug & 63;
            size_t o = ((size_t)(m >> 7) * 2 + kc) * 8192 + (size_t)row * 64
                       + (cc ^ ((row & 7) << 3));
            __nv_bfloat16 h = __float2bfloat16(v);
            ctile[o] = h;
            ctile[(size_t)BMAX * 128 + o] = __float2bfloat16(v - __bfloat162float(h));
        }
    }
}

// ---------------------------------------------------------------------------
// fused GRU cell (tile activations). mode 0: gate epilogue; mode 1: gi_out.
// ---------------------------------------------------------------------------
__global__ __launch_bounds__(256) void gru_mma3(
    const __nv_bfloat16* __restrict__ At, int aK, int k1, long wih_off,
    const __nv_bfloat16* __restrict__ Ht, int htiles, long whh_off,
    const float* __restrict__ gi_ext, const float* __restrict__ wdyn,
    const float* __restrict__ xdyn,
    const float* __restrict__ bih, const float* __restrict__ bhh,
    __nv_bfloat16* __restrict__ HoutT, float* __restrict__ gi_out, int B, int mode) {
    extern __shared__ char sm_[];
    float* gbuf = (float*)sm_;
    float* wd_s = (float*)(sm_ + OFF_WDS);
    const int tid = threadIdx.x, lane = tid & 31, w = tid >> 5;
    const int mw = w >> 1, nw = w & 1;
    const int m0 = blockIdx.x * 128;
    const int by = blockIdx.y, n0 = by * 32;

    float accA[2][6][4], accH[2][2][4];
#pragma unroll
    for (int mf = 0; mf < 2; mf++) {
#pragma unroll
        for (int f = 0; f < 6; f++)
#pragma unroll
            for (int u = 0; u < 4; u++) accA[mf][f][u] = 0.f;
#pragma unroll
        for (int f = 0; f < 2; f++)
#pragma unroll
            for (int u = 0; u < 4; u++) accH[mf][f][u] = 0.f;
    }

    const int C = k1 + htiles;
    const size_t aLoE = (size_t)BMAX * aK * 64;
    const size_t hLoE = (size_t)BMAX * 256;

    auto src_stage = [&](int c, char* bb) {
        if (c < k1)
            stage_chunk(bb, At + ((size_t)(m0 >> 7) * aK + c) * 8192, aLoE,
                        wih_off + ((long)c * 8 + by) * 6144, tid);
        else
            stage_chunk(bb, Ht + ((size_t)(m0 >> 7) * 4 + (c - k1)) * 8192, hLoE,
                        whh_off + ((long)(c - k1) * 8 + by) * 6144, tid);
    };

    if (C > 0) src_stage(0, sm_);
    for (int c = 0; c < C; c++) {
        if (c + 1 < C) { src_stage(c + 1, sm_ + ((c + 1) & 1) * BUFSZ); cp_wait1(); }
        else cp_wait0();
        __syncthreads();
        if (c >= k1) mma_tile<true>(sm_ + (c & 1) * BUFSZ, accA, accH, mw, nw, lane);
        else         mma_tile<false>(sm_ + (c & 1) * BUFSZ, accA, accH, mw, nw, lane);
        __syncthreads();
    }

    // dyn weight cache (tiny), loaded after GEMM into dead buffer space
    if (wdyn != nullptr) {
        for (int i = tid; i < 768; i += 256) {
            int rr = i >> 3, q = i & 7;
            int p = rr >> 5, c = rr & 31;
            wd_s[i] = wdyn[((size_t)(p * 256) + n0 + c) * 8 + q];
        }
    }

    // scatter accumulators to gate buffer (4 planes x 128 x 36)
    {
        int r0 = mw * 32 + (lane >> 2);
        int cl = (lane & 3) * 2;
#pragma unroll
        for (int mf = 0; mf < 2; mf++) {
#pragma unroll
            for (int f = 0; f < 6; f++) {
                int gf = f * 2 + nw;
                int p = gf >> 2;
                int col = ((gf * 8) & 31) + cl;
                int rr = r0 + mf * 16;
                float* g0 = gbuf + ((size_t)(p * 128 + rr)) * 36 + col;
                g0[0] = accA[mf][f][0]; g0[1] = accA[mf][f][1];
                g0[8 * 36] = accA[mf][f][2]; g0[8 * 36 + 1] = accA[mf][f][3];
                if (f >= 4) {
                    float* g1 = gbuf + ((size_t)(3 * 128 + rr)) * 36 + col;
                    g1[0] = accH[mf][f - 4][0]; g1[1] = accH[mf][f - 4][1];
                    g1[8 * 36] = accH[mf][f - 4][2]; g1[8 * 36 + 1] = accH[mf][f - 4][3];
                }
            }
        }
    }
    __syncthreads();

    if (mode == 1) {
        for (int i = tid; i < 3 * 128 * 32; i += 256) {
            int p = i >> 12; int rem = i & 4095;
            int row = rem >> 5; int col = rem & 31;
            int m = m0 + row;
            if (m < B)
                gi_out[(size_t)m * 768 + p * 256 + n0 + col] =
                    gbuf[(size_t)(p * 128 + row) * 36 + col];
        }
        return;
    }

    // ---- gate epilogue ----
    {
        int row = tid >> 1;
        int m = m0 + row;
        int cg = (tid & 1) * 16;
        bool valid = (m < B);
        // h_prev from tiles (hi+lo)
        int kc = by >> 1;
        int cc = (by & 1) * 32 + cg;
        size_t tE = ((size_t)(m0 >> 7) * 4 + kc) * 8192 + (size_t)row * 64;
        int u0 = cc ^ ((row & 7) << 3);
        int u1 = (cc + 8) ^ ((row & 7) << 3);
        float hp[16];
        {
            uint4 h0 = *(const uint4*)(Ht + tE + u0);
            uint4 h1 = *(const uint4*)(Ht + tE + u1);
            uint4 l0 = *(const uint4*)(Ht + hLoE + tE + u0);
            uint4 l1 = *(const uint4*)(Ht + hLoE + tE + u1);
            const __nv_bfloat162* ph0 = (const __nv_bfloat162*)&h0;
            const __nv_bfloat162* ph1 = (const __nv_bfloat162*)&h1;
            const __nv_bfloat162* pl0 = (const __nv_bfloat162*)&l0;
            const __nv_bfloat162* pl1 = (const __nv_bfloat162*)&l1;
#pragma unroll
            for (int q = 0; q < 4; q++) {
                hp[q * 2 + 0] = __bfloat162float(ph0[q].x) + __bfloat162float(pl0[q].x);
                hp[q * 2 + 1] = __bfloat162float(ph0[q].y) + __bfloat162float(pl0[q].y);
                hp[8 + q * 2 + 0] = __bfloat162float(ph1[q].x) + __bfloat162float(pl1[q].x);
                hp[8 + q * 2 + 1] = __bfloat162float(ph1[q].y) + __bfloat162float(pl1[q].y);
            }
        }
        float xd[6] = {0, 0, 0, 0, 0, 0};
        if (wdyn != nullptr && valid)
#pragma unroll
            for (int q = 0; q < 6; q++) xd[q] = xdyn[(size_t)m * 6 + q];

        float ov[16];
#pragma unroll
        for (int c4 = 0; c4 < 4; c4++) {
            int col = cg + c4 * 4;
            int jg = n0 + col;
            float grv[4], gzv[4], giv[4], ghv[4];
            *(float4*)grv = *(float4*)(gbuf + (size_t)(0 * 128 + row) * 36 + col);
            *(float4*)gzv = *(float4*)(gbuf + (size_t)(1 * 128 + row) * 36 + col);
            *(float4*)giv = *(float4*)(gbuf + (size_t)(2 * 128 + row) * 36 + col);
            *(float4*)ghv = *(float4*)(gbuf + (size_t)(3 * 128 + row) * 36 + col);
            if (gi_ext != nullptr && valid) {
                float e0[4], e1[4], e2[4];
                *(float4*)e0 = *(const float4*)(gi_ext + (size_t)m * 768 + jg);
                *(float4*)e1 = *(const float4*)(gi_ext + (size_t)m * 768 + 256 + jg);
                *(float4*)e2 = *(const float4*)(gi_ext + (size_t)m * 768 + 512 + jg);
#pragma unroll
                for (int q = 0; q < 4; q++) {
                    grv[q] += e0[q]; gzv[q] += e1[q]; giv[q] += e2[q];
                }
            }
            if (wdyn != nullptr) {
#pragma unroll
                for (int q4 = 0; q4 < 4; q4++) {
                    int cl_ = col + q4;
                    const float* w0 = wd_s + (0 * 32 + cl_) * 8;
                    const float* w1 = wd_s + (1 * 32 + cl_) * 8;
                    const float* w2 = wd_s + (2 * 32 + cl_) * 8;
#pragma unroll
                    for (int q = 0; q < 6; q++) {
                        grv[q4] += xd[q] * w0[q];
                        gzv[q4] += xd[q] * w1[q];
                        giv[q4] += xd[q] * w2[q];
                    }
                }
            }
#pragma unroll
            for (int q = 0; q < 4; q++) {
                int j = jg + q;
                float r_ = 1.f / (1.f + expf(-(grv[q] + bih[j] + bhh[j])));
                float z_ = 1.f / (1.f + expf(-(gzv[q] + bih[256 + j] + bhh[256 + j])));
                float n_ = tanhf(giv[q] + bih[512 + j] + r_ * (ghv[q] + bhh[512 + j]));
                ov[c4 * 4 + q] = (1.f - z_) * n_ + z_ * hp[c4 * 4 + q];
            }
        }
        if (valid) {
            __nv_bfloat162 hhv[8], llv[8];
#pragma unroll
            for (int q = 0; q < 8; q++) {
                float a = ov[q * 2], b = ov[q * 2 + 1];
                __nv_bfloat162 h2 = __floats2bfloat162_rn(a, b);
                hhv[q] = h2;
                llv[q] = __floats2bfloat162_rn(a - __bfloat162float(h2.x),
                                               b - __bfloat162float(h2.y));
            }
            *(uint4*)(HoutT + tE + u0) = *(uint4*)&hhv[0];
            *(uint4*)(HoutT + tE + u1) = *(uint4*)&hhv[4];
            *(uint4*)(HoutT + hLoE + tE + u0) = *(uint4*)&llv[0];
            *(uint4*)(HoutT + hLoE + tE + u1) = *(uint4*)&llv[4];
        }
    }
}

// ---------------------------------------------------------------------------
// projection: 8-chunk pipelined GEMM (two 96-col phases), GELU -> D1, heads.
// ---------------------------------------------------------------------------
__device__ __forceinline__ void proj_scatter(float (&accA)[2][6][4], float* D1, int n0,
                                             const float* __restrict__ p1b,
                                             const float* __restrict__ a1b,
                                             int mw, int nw, int lane) {
    int r0 = mw * 32 + (lane >> 2);
    int cl = (lane & 3) * 2;
#pragma unroll
    for (int mf = 0; mf < 2; mf++)
#pragma unroll
        for (int f = 0; f < 6; f++) {
            int gf = f * 2 + nw;
            int colb = n0 + gf * 8 + cl;
            int rr = r0 + mf * 16;
#pragma unroll
            for (int jj = 0; jj < 2; jj++) {
                int col = colb + jj;
                float b = (col < 128) ? p1b[col] : a1b[col - 128];
                float v0 = accA[mf][f][jj] + b;
                float v1 = accA[mf][f][2 + jj] + b;
                D1[(size_t)rr * 196 + col] = v0 * normcdff(v0);
                D1[(size_t)(rr + 8) * 196 + col] = v1 * normcdff(v1);
            }
        }
}

__global__ __launch_bounds__(256) void proj_mma3(
    const __nv_bfloat16* __restrict__ Ht,
    const float* __restrict__ p1b, const float* __restrict__ a1b,
    const float* __restrict__ P2, const float* __restrict__ p2b,
    const float* __restrict__ A2, const float* __restrict__ a2b,
    float* __restrict__ out, float* __restrict__ dyn, int B, int tstep) {
    extern __shared__ char sm_[];
    float* D1 = (float*)(sm_ + OFF_D1);
    float* wsm = (float*)(sm_ + OFF_WSM);
    const int tid = threadIdx.x, lane = tid & 31, w = tid >> 5;
    const int mw = w >> 1, nw = w & 1;
    const int m0 = blockIdx.x * 128;
    const size_t hLoE = (size_t)BMAX * 256;

    // head weights
    for (int i = tid; i < 648; i += 256) {
        float v;
        if (i < 512) v = P2[i];
        else if (i < 640) v = A2[i - 512];
        else if (i < 644) v = p2b[i - 640];
        else v = a2b[i - 644];
        wsm[i] = v;
    }

    float accA[2][6][4], accH[2][2][4];
#pragma unroll
    for (int mf = 0; mf < 2; mf++) {
#pragma unroll
        for (int f = 0; f < 6; f++)
#pragma unroll
            for (int u = 0; u < 4; u++) accA[mf][f][u] = 0.f;
#pragma unroll
        for (int f = 0; f < 2; f++)
#pragma unroll
            for (int u = 0; u < 4; u++) accH[mf][f][u] = 0.f;
    }

    auto src_stage = [&](int c, char* bb) {
        int kc = c & 3, ph = c >> 2;
        stage_chunk(bb, Ht + ((size_t)(m0 >> 7) * 4 + kc) * 8192, hLoE,
                    O_PA + ((long)kc * 192 + ph * 96) * 64, tid);
    };

    src_stage(0, sm_);
    for (int c = 0; c < 8; c++) {
        if (c + 1 < 8) { src_stage(c + 1, sm_ + ((c + 1) & 1) * BUFSZ); cp_wait1(); }
        else cp_wait0();
        __syncthreads();
        mma_tile<false>(sm_ + (c & 1) * BUFSZ, accA, accH, mw, nw, lane);
        __syncthreads();
        if (c == 3) {
            proj_scatter(accA, D1, 0, p1b, a1b, mw, nw, lane);
#pragma unroll
            for (int mf = 0; mf < 2; mf++)
#pragma unroll
                for (int f = 0; f < 6; f++)
#pragma unroll
                    for (int u = 0; u < 4; u++) accA[mf][f][u] = 0.f;
        }
    }
    proj_scatter(accA, D1, 96, p1b, a1b, mw, nw, lane);
    __syncthreads();

    // delta head: 128 rows x 4 outs, K=128
#pragma unroll
    for (int it = 0; it < 2; it++) {
        int idx = tid + it * 256;
        int s = idx >> 2, o = idx & 3;
        float a = wsm[640 + o];
        const float* w2 = wsm + o * 128;
        const float* d = D1 + (size_t)s * 196;
#pragma unroll 8
        for (int k = 0; k < 128; k++) a += d[k] * w2[k];
        int m = m0 + s;
        if (m < B) {
            out[(size_t)m * 48 + tstep * 4 + o] = a;
            dyn[(size_t)m * 6 + (o < 2 ? o : o + 2)] = a;
        }
    }
    // accel head: 128 rows x 2 outs, K=64
    {
        int s = tid >> 1, o = tid & 1;
        float a = wsm[644 + o];
        const float* w2 = wsm + 512 + o * 64;
        const float* d = D1 + (size_t)s * 196 + 128;
#pragma unroll 8
        for (int k = 0; k < 64; k++) a += d[k] * w2[k];
        int m = m0 + s;
        if (m < B) dyn[(size_t)m * 6 + 2 + o] = a;
    }
}

// ---------------------------------------------------------------------------
extern "C" void kernel_launch(void* const* d_in, const int* in_sizes, int n_in,
                              void* d_out, int out_size) {
    const float* ctx      = (const float*)d_in[0];
    const float* obs_traj = (const float*)d_in[1];
    const float* obs_Me   = (const float*)d_in[2];
    const float* Wih0 = (const float*)d_in[3];
    const float* Whh0 = (const float*)d_in[4];
    const float* bih0 = (const float*)d_in[5];
    const float* bhh0 = (const float*)d_in[6];
    const float* Wih1 = (const float*)d_in[7];
    const float* Whh1 = (const float*)d_in[8];
    const float* bih1 = (const float*)d_in[9];
    const float* bhh1 = (const float*)d_in[10];
    const float* Wihs = (const float*)d_in[11];
    const float* Whhs = (const float*)d_in[12];
    const float* bihs = (const float*)d_in[13];
    const float* bhhs = (const float*)d_in[14];
    const float* P1  = (const float*)d_in[15];
    const float* p1b = (const float*)d_in[16];
    const float* P2  = (const float*)d_in[17];
    const float* p2b = (const float*)d_in[18];
    const float* A1  = (const float*)d_in[19];
    const float* a1b = (const float*)d_in[20];
    const float* A2  = (const float*)d_in[21];
    const float* a2b = (const float*)d_in[22];
    const float* Cw  = (const float*)d_in[23];
    const float* cb  = (const float*)d_in[24];
    float* out = (float*)d_out;

    int B = in_sizes[0] / CTXD;
    if (B > BMAX) B = BMAX;
    int T = in_sizes[1] / (2 * B);
    int TS = T - 1;

    __nv_bfloat16 *t0a, *t0b, *t1a, *t1b, *ctile, *wpk;
    float *obsin, *dynA, *dynB, *gictx, *wd0, *wdS;
    cudaGetSymbolAddress((void**)&t0a, g_t0a);
    cudaGetSymbolAddress((void**)&t0b, g_t0b);
    cudaGetSymbolAddress((void**)&t1a, g_t1a);
    cudaGetSymbolAddress((void**)&t1b, g_t1b);
    cudaGetSymbolAddress((void**)&ctile, g_ctile);
    cudaGetSymbolAddress((void**)&obsin, g_obsin);
    cudaGetSymbolAddress((void**)&dynA, g_dynA);
    cudaGetSymbolAddress((void**)&dynB, g_dynB);
    cudaGetSymbolAddress((void**)&gictx, g_gictx);
    cudaGetSymbolAddress((void**)&wd0, g_wdyn0);
    cudaGetSymbolAddress((void**)&wdS, g_wdynS);
    cudaGetSymbolAddress((void**)&wpk, g_wpack);

    cudaFuncSetAttribute(gru_mma3, cudaFuncAttributeMaxDynamicSharedMemorySize, GRU_SMEM);
    cudaFuncSetAttribute(proj_mma3, cudaFuncAttributeMaxDynamicSharedMemorySize, PROJ_SMEM);

    pack_cellw<<<768, 256>>>(Whh0, 256, 0, 256, 4, O_WHH0, wpk);
    pack_cellw<<<768, 256>>>(Wih1, 256, 0, 256, 4, O_WIH1, wpk);
    pack_cellw<<<768, 256>>>(Whh1, 256, 0, 256, 4, O_WHH1, wpk);
    pack_cellw<<<768, 256>>>(Whhs, 256, 0, 256, 4, O_WHHS, wpk);
    pack_cellw<<<384, 256>>>(Wihs, 134, 0, 128, 2, O_WCTX, wpk);
    pack_paw<<<192, 256>>>(P1, A1, wpk);
    wdyn_pack_kernel<<<24, 256>>>(Wih0, 6, 0, wd0);
    wdyn_pack_kernel<<<24, 256>>>(Wihs, 134, 128, wdS);

    // zero initial hidden tiles (hi+lo planes; bf16 zero == bit zero)
    zero_kernel<<<264, 256>>>((float*)t0a, BMAX * HDIM);
    zero_kernel<<<264, 256>>>((float*)t1a, BMAX * HDIM);
    prep_kernel<<<(B + 255) / 256, 256>>>(obs_traj, obs_Me, obsin, dynA, B, T);
    ctx_kernel<<<(B + 63) / 64, 256>>>(ctx, Cw, cb, ctile, B);

    dim3 cgrid((B + 127) / 128, 8);

    // hoisted decoder ctx input-gates (mode 1)
    gru_mma3<<<cgrid, 256, GRU_SMEM>>>(ctile, 2, 2, O_WCTX,
                                       t1a, 0, 0L,
                                       nullptr, nullptr, nullptr,
                                       bihs, bhhs, nullptr, gictx, B, 1);

    __nv_bfloat16 *h0i = t0a, *h0o = t0b, *h1i = t1a, *h1o = t1b;
    for (int t = 0; t < TS; t++) {
        gru_mma3<<<cgrid, 256, GRU_SMEM>>>(nullptr, 4, 0, 0L,
                                           h0i, (t > 0) ? 4 : 0, O_WHH0,
                                           nullptr, wd0, obsin + (size_t)t * B * 6,
                                           bih0, bhh0, h0o, nullptr, B, 0);
        gru_mma3<<<cgrid, 256, GRU_SMEM>>>(h0o, 4, 4, O_WIH1,
                                           h1i, (t > 0) ? 4 : 0, O_WHH1,
                                           nullptr, nullptr, nullptr,
                                           bih1, bhh1, h1o, nullptr, B, 0);
        __nv_bfloat16* a = h0i; h0i = h0o; h0o = a;
        __nv_bfloat16* b = h1i; h1i = h1o; h1o = b;
    }

    __nv_bfloat16 *dhi = h1i, *dho = h1o;
    float *dyi = dynA, *dyo = dynB;
    for (int s = 0; s < PRED; s++) {
        gru_mma3<<<cgrid, 256, GRU_SMEM>>>(nullptr, 4, 0, 0L,
                                           dhi, 4, O_WHHS,
                                           gictx, wdS, dyi,
                                           bihs, bhhs, dho, nullptr, B, 0);
        proj_mma3<<<(B + 127) / 128, 256, PROJ_SMEM>>>(dho, p1b, a1b, P2, p2b,
                                                       A2, a2b, out, dyo, B, s);
        __nv_bfloat16* a = dhi; dhi = dho; dho = a;
        float* b = dyi; dyi = dyo; dyo = b;
    }
}